// round 2
// baseline (speedup 1.0000x reference)
#include <cuda_runtime.h>
#include <cstdint>

#define N_BAGS 4
#define P_PATCH 20000
#define DIN 1024
#define ROWS (N_BAGS*P_PATCH)   /* 80000 */
#define M_TILE 128
#define GRID1 (ROWS/M_TILE)     /* 625, exact */
#define NB 72                   /* 64 proj cols + 8 centroid cols */
#define XS_STRIDE 36
#define EP_STRIDE 76

/* scratch (no allocation allowed) */
__device__ unsigned char g_assign[ROWS];
__device__ float g_S[32*64];
__device__ int   g_counts[32];

static __device__ __forceinline__ uint32_t tf32_bits(float f){
    uint32_t u; asm("cvt.rna.tf32.f32 %0, %1;" : "=r"(u) : "f"(f)); return u;
}
static __device__ __forceinline__ float tf32f(float f){ return __uint_as_float(tf32_bits(f)); }

static __device__ __forceinline__ void mma8(float* c,
    uint32_t a0, uint32_t a1, uint32_t a2, uint32_t a3, uint32_t b0, uint32_t b1)
{
    asm volatile(
      "mma.sync.aligned.m16n8k8.row.col.f32.tf32.tf32.f32 "
      "{%0,%1,%2,%3},{%4,%5,%6,%7},{%8,%9},{%0,%1,%2,%3};\n"
      : "+f"(c[0]), "+f"(c[1]), "+f"(c[2]), "+f"(c[3])
      : "r"(a0), "r"(a1), "r"(a2), "r"(a3), "r"(b0), "r"(b1));
}

/* ------------------------------------------------------------------ */
/* Kernel 1: fused  xp = relu(x@Wpre + b)  (written to both outputs), */
/* centroid dots -> hard assignment byte per row.                     */
/* ------------------------------------------------------------------ */
__global__ __launch_bounds__(256) void k1(
    const float* __restrict__ x, const float* __restrict__ centroids,
    const float* __restrict__ W_pre, const float* __restrict__ b_pre,
    float* __restrict__ O1, float* __restrict__ O2)
{
    __shared__ float sp[9992];
    float* xs  = sp;           /* [128][36]  staging of x chunk (tf32-rounded) */
    float* Bs  = sp + 4608;    /* [32][72]   staging of B chunk */
    float* ep  = sp;           /* [128][76]  epilogue (aliases xs/Bs)          */
    float* x2p = sp + 9728;    /* [256] per-thread x^2 partials                */
    float* c2s = sp + 9984;    /* [8] centroid squared norms                   */

    const int t = threadIdx.x, warp = t >> 5, lane = t & 31;
    const int gid = lane >> 2, tig = lane & 3;
    const int rowBase = blockIdx.x * M_TILE;

    /* exact fp32 centroid norms: warp w handles centroid w */
    {
        float s = 0.f;
        const float* c = centroids + (size_t)warp * DIN;
        for (int d = lane; d < DIN; d += 32) { float v = c[d]; s = fmaf(v, v, s); }
        #pragma unroll
        for (int o = 16; o; o >>= 1) s += __shfl_xor_sync(0xffffffffu, s, o);
        if (lane == 0) c2s[warp] = s;
    }

    float acc[9][4];
    #pragma unroll
    for (int i = 0; i < 9; i++) { acc[i][0]=acc[i][1]=acc[i][2]=acc[i][3]=0.f; }
    float x2acc = 0.f;

    const int lrow = t >> 1, lcb = (t & 1) * 16;
    const int wrow = warp * 16;

    for (int kc = 0; kc < DIN; kc += 32) {
        __syncthreads();
        /* stage x chunk (and accumulate exact fp32 squares) */
        {
            const float4* xg = (const float4*)(x + (size_t)(rowBase + lrow) * DIN + kc + lcb);
            #pragma unroll
            for (int i = 0; i < 4; i++) {
                float4 v = xg[i];
                x2acc += v.x*v.x + v.y*v.y + v.z*v.z + v.w*v.w;
                float4 w;
                w.x = tf32f(v.x); w.y = tf32f(v.y); w.z = tf32f(v.z); w.w = tf32f(v.w);
                *(float4*)(xs + lrow * XS_STRIDE + lcb + 4*i) = w;
            }
        }
        /* stage B chunk: cols 0..63 = W_pre rows, cols 64..71 = centroids^T */
        {
            #pragma unroll
            for (int j = 0; j < 2; j++) {
                int idx = t + 256 * j;
                int r = idx >> 4, c4 = idx & 15;
                float4 v = ((const float4*)(W_pre + (size_t)(kc + r) * 64))[c4];
                float4 w;
                w.x = tf32f(v.x); w.y = tf32f(v.y); w.z = tf32f(v.z); w.w = tf32f(v.w);
                *(float4*)(Bs + r * NB + c4 * 4) = w;
            }
            int ck = t >> 5, cr = lane;
            Bs[cr * NB + 64 + ck] = tf32f(centroids[(size_t)ck * DIN + kc + cr]);
        }
        __syncthreads();
        /* MMA: warp computes its 16x72 tile */
        #pragma unroll
        for (int kk = 0; kk < 32; kk += 8) {
            uint32_t a0 = __float_as_uint(xs[(wrow + gid    ) * XS_STRIDE + kk + tig    ]);
            uint32_t a1 = __float_as_uint(xs[(wrow + gid + 8) * XS_STRIDE + kk + tig    ]);
            uint32_t a2 = __float_as_uint(xs[(wrow + gid    ) * XS_STRIDE + kk + tig + 4]);
            uint32_t a3 = __float_as_uint(xs[(wrow + gid + 8) * XS_STRIDE + kk + tig + 4]);
            #pragma unroll
            for (int nt = 0; nt < 9; nt++) {
                uint32_t b0 = __float_as_uint(Bs[(kk + tig    ) * NB + nt * 8 + gid]);
                uint32_t b1 = __float_as_uint(Bs[(kk + tig + 4) * NB + nt * 8 + gid]);
                mma8(acc[nt], a0, a1, a2, a3, b0, b1);
            }
        }
    }
    __syncthreads();
    /* stash accumulators into smem epilogue tile */
    #pragma unroll
    for (int nt = 0; nt < 9; nt++) {
        int c0 = nt * 8 + 2 * tig;
        ep[(wrow + gid    ) * EP_STRIDE + c0    ] = acc[nt][0];
        ep[(wrow + gid    ) * EP_STRIDE + c0 + 1] = acc[nt][1];
        ep[(wrow + gid + 8) * EP_STRIDE + c0    ] = acc[nt][2];
        ep[(wrow + gid + 8) * EP_STRIDE + c0 + 1] = acc[nt][3];
    }
    x2p[t] = x2acc;
    __syncthreads();
    /* vectorized relu(+bias) store to both output copies */
    {
        const int cb = (t & 1) * 32;
        #pragma unroll
        for (int i = 0; i < 8; i++) {
            int c = cb + 4 * i;
            float4 v = *(const float4*)(ep + lrow * EP_STRIDE + c);
            float4 b = *(const float4*)(b_pre + c);
            v.x = fmaxf(v.x + b.x, 0.f); v.y = fmaxf(v.y + b.y, 0.f);
            v.z = fmaxf(v.z + b.z, 0.f); v.w = fmaxf(v.w + b.w, 0.f);
            size_t go = (size_t)(rowBase + lrow) * 64 + c;
            *(float4*)(O1 + go) = v;
            *(float4*)(O2 + go) = v;
        }
    }
    /* hard assignment: softmax(1e7/dist) > 0.5  <=>  s < 2 at argmax */
    if (t < 128) {
        float x2 = x2p[2*t] + x2p[2*t + 1];
        float z[8], m = -3.4e38f;
        #pragma unroll
        for (int k = 0; k < 8; k++) {
            float dot = ep[t * EP_STRIDE + 64 + k];
            float d2  = fmaxf(x2 + c2s[k] - 2.0f * dot, 0.0f);
            float zk  = 1e7f / sqrtf(d2);
            z[k] = zk; m = fmaxf(m, zk);
        }
        float s = 0.f; int am = 0;
        #pragma unroll
        for (int k = 0; k < 8; k++) { s += expf(z[k] - m); if (z[k] == m) am = k; }
        g_assign[rowBase + t] = (s < 2.0f) ? (unsigned char)am : (unsigned char)255;
    }
}

/* ------------------------------------------------------------------ */
/* Kernel 2: per-(n,k) cluster sums + counts (contention-free).       */
/* ------------------------------------------------------------------ */
__global__ __launch_bounds__(256) void k2(const float* __restrict__ O1)
{
    __shared__ float part[8][64];
    __shared__ int pcnt[8];
    const int t = threadIdx.x, warp = t >> 5, lane = t & 31;
    const int n = blockIdx.x >> 3, k = blockIdx.x & 7;
    float sx = 0.f, sy = 0.f; int cnt = 0;
    const size_t base = (size_t)n * P_PATCH;
    for (int p = warp; p < P_PATCH; p += 8) {
        int a = g_assign[base + p];
        if (a == k) {
            cnt++;
            float2 v = ((const float2*)(O1 + (base + p) * 64))[lane];
            sx += v.x; sy += v.y;
        }
    }
    part[warp][2*lane] = sx; part[warp][2*lane + 1] = sy;
    if (lane == 0) pcnt[warp] = cnt;
    __syncthreads();
    if (t < 64) {
        float s = 0.f;
        #pragma unroll
        for (int w = 0; w < 8; w++) s += part[w][t];
        g_S[(n * 8 + k) * 64 + t] = s;
    }
    if (t == 0) { int c = 0; for (int w = 0; w < 8; w++) c += pcnt[w]; g_counts[n * 8 + k] = c; }
}

/* ------------------------------------------------------------------ */
/* Kernel 3: attention MLP + masked softmax + enc_cls (tiny).         */
/* ------------------------------------------------------------------ */
__global__ __launch_bounds__(128) void k3(
    const float* __restrict__ W_a1, const float* __restrict__ b_a1,
    const float* __restrict__ W_a2, const float* __restrict__ b_a2,
    const float* __restrict__ W_out, const float* __restrict__ b_out,
    float* __restrict__ out)
{
    __shared__ float Aa[4][8];
    __shared__ float pool[4][64];
    const int t = threadIdx.x, n = t >> 5, lane = t & 31;

    for (int k = 0; k < 8; k++) {
        int cnt = g_counts[n * 8 + k];
        float inv = cnt > 0 ? 1.0f / (float)cnt : 0.0f;
        const float* S = g_S + (n * 8 + k) * 64;
        float h = b_a1[lane];
        #pragma unroll
        for (int d = 0; d < 64; d++) h = fmaf(S[d] * inv, W_a1[d * 32 + lane], h);
        h = tanhf(h);
        float c = h * W_a2[lane];
        #pragma unroll
        for (int o = 16; o; o >>= 1) c += __shfl_xor_sync(0xffffffffu, c, o);
        if (lane == 0) Aa[n][k] = (cnt > 0) ? (c + b_a2[0]) : -100000.0f;
    }
    __syncwarp();
    float m = -3.4e38f;
    #pragma unroll
    for (int k = 0; k < 8; k++) m = fmaxf(m, Aa[n][k]);
    float e[8], s = 0.f;
    #pragma unroll
    for (int k = 0; k < 8; k++) { e[k] = expf(Aa[n][k] - m); s += e[k]; }
    float p0 = 0.f, p1 = 0.f;
    #pragma unroll
    for (int k = 0; k < 8; k++) {
        int cnt = g_counts[n * 8 + k];
        float inv = cnt > 0 ? 1.0f / (float)cnt : 0.0f;
        float w = (e[k] / s) * inv;
        p0 = fmaf(g_S[(n * 8 + k) * 64 + lane     ], w, p0);
        p1 = fmaf(g_S[(n * 8 + k) * 64 + lane + 32], w, p1);
    }
    pool[n][lane] = p0; pool[n][lane + 32] = p1;
    __syncwarp();
    float ec = b_out[lane];
    #pragma unroll
    for (int d = 0; d < 64; d++) ec = fmaf(pool[n][d], W_out[d * 32 + lane], ec);
    out[n * 32 + lane] = fmaxf(ec, 0.f);
}

/* ------------------------------------------------------------------ */
extern "C" void kernel_launch(void* const* d_in, const int* in_sizes, int n_in,
                              void* d_out, int out_size)
{
    const float* x         = (const float*)d_in[0];
    const float* centroids = (const float*)d_in[1];
    const float* W_pre     = (const float*)d_in[2];
    const float* b_pre     = (const float*)d_in[3];
    const float* W_a1      = (const float*)d_in[4];
    const float* b_a1      = (const float*)d_in[5];
    const float* W_a2      = (const float*)d_in[6];
    const float* b_a2      = (const float*)d_in[7];
    const float* W_out     = (const float*)d_in[8];
    const float* b_out     = (const float*)d_in[9];

    float* out = (float*)d_out;
    float* O1 = out + 128;                         /* enc_seq copy 1 */
    float* O2 = out + 128 + (size_t)ROWS * 64;     /* enc_seq copy 2 */

    k1<<<GRID1, 256>>>(x, centroids, W_pre, b_pre, O1, O2);
    k2<<<32, 256>>>(O1);
    k3<<<1, 128>>>(W_a1, b_a1, W_a2, b_a2, W_out, b_out, out);
}

// round 4
// speedup vs baseline: 2.1012x; 2.1012x over previous
#include <cuda_runtime.h>
#include <cstdint>

#define N_BAGS 4
#define P_PATCH 20000
#define DIN 1024
#define ROWS (N_BAGS*P_PATCH)   /* 80000 */
#define M_TILE 128
#define GRID1 (ROWS/M_TILE)     /* 625, exact */
#define NB 72                   /* 64 proj cols + 8 centroid cols */
#define XS_STRIDE 36
#define EP_STRIDE 76

/* scratch (no allocation allowed) */
__device__ float g_S[32*64];
__device__ int   g_counts[32];
__device__ float g_c2[8];

static __device__ __forceinline__ uint32_t tf32_bits(float f){
    uint32_t u; asm("cvt.rna.tf32.f32 %0, %1;" : "=r"(u) : "f"(f)); return u;
}
static __device__ __forceinline__ float tf32f(float f){ return __uint_as_float(tf32_bits(f)); }

static __device__ __forceinline__ void mma8(float* c,
    uint32_t a0, uint32_t a1, uint32_t a2, uint32_t a3, uint32_t b0, uint32_t b1)
{
    asm volatile(
      "mma.sync.aligned.m16n8k8.row.col.f32.tf32.tf32.f32 "
      "{%0,%1,%2,%3},{%4,%5,%6,%7},{%8,%9},{%0,%1,%2,%3};\n"
      : "+f"(c[0]), "+f"(c[1]), "+f"(c[2]), "+f"(c[3])
      : "r"(a0), "r"(a1), "r"(a2), "r"(a3), "r"(b0), "r"(b1));
}

/* ------------------------------------------------------------------ */
/* Kernel 0: zero accumulators + centroid squared norms (tiny).       */
/* ------------------------------------------------------------------ */
__global__ __launch_bounds__(256) void k0(const float* __restrict__ centroids)
{
    const int t = threadIdx.x, warp = t >> 5, lane = t & 31;
    for (int i = t; i < 32*64; i += 256) g_S[i] = 0.f;
    if (t < 32) g_counts[t] = 0;
    float s = 0.f;
    const float* c = centroids + (size_t)warp * DIN;
    for (int d = lane; d < DIN; d += 32) { float v = c[d]; s = fmaf(v, v, s); }
    #pragma unroll
    for (int o = 16; o; o >>= 1) s += __shfl_xor_sync(0xffffffffu, s, o);
    if (lane == 0) g_c2[warp] = s;
}

/* ------------------------------------------------------------------ */
/* Kernel 1: fused  xp = relu(x@Wpre + b) (dual store), centroid dots */
/* -> hard assignment, AND per-(n,k) cluster sum/count accumulation.  */
/* ------------------------------------------------------------------ */
__global__ __launch_bounds__(256) void k1(
    const float* __restrict__ x, const float* __restrict__ centroids,
    const float* __restrict__ W_pre, const float* __restrict__ b_pre,
    float* __restrict__ O1, float* __restrict__ O2)
{
    __shared__ float sp[9992];
    __shared__ float part[8][8][32];      /* [warp][k][col32] partials */
    __shared__ unsigned char sAssign[128];
    float* xs  = sp;           /* [128][36] staging of x chunk (tf32)  */
    float* Bs  = sp + 4608;    /* [32][72]  staging of B chunk         */
    float* ep  = sp;           /* [128][76] epilogue (aliases xs/Bs)   */
    float* x2p = sp + 9728;    /* [256] per-thread x^2 partials        */
    float* c2s = sp + 9984;    /* [8] centroid squared norms           */

    const int t = threadIdx.x, warp = t >> 5, lane = t & 31;
    const int gid = lane >> 2, tig = lane & 3;
    const int rowBase = blockIdx.x * M_TILE;

    if (t < 8) c2s[t] = g_c2[t];

    float acc[9][4];
    #pragma unroll
    for (int i = 0; i < 9; i++) { acc[i][0]=acc[i][1]=acc[i][2]=acc[i][3]=0.f; }
    float x2acc = 0.f;

    const int lrow = t >> 1, lcb = (t & 1) * 16;
    const int wrow = warp * 16;

    for (int kc = 0; kc < DIN; kc += 32) {
        __syncthreads();
        /* stage x chunk (and accumulate exact fp32 squares) */
        {
            const float4* xg = (const float4*)(x + (size_t)(rowBase + lrow) * DIN + kc + lcb);
            #pragma unroll
            for (int i = 0; i < 4; i++) {
                float4 v = xg[i];
                x2acc += v.x*v.x + v.y*v.y + v.z*v.z + v.w*v.w;
                float4 w;
                w.x = tf32f(v.x); w.y = tf32f(v.y); w.z = tf32f(v.z); w.w = tf32f(v.w);
                *(float4*)(xs + lrow * XS_STRIDE + lcb + 4*i) = w;
            }
        }
        /* stage B chunk: cols 0..63 = W_pre rows, cols 64..71 = centroids^T */
        {
            #pragma unroll
            for (int j = 0; j < 2; j++) {
                int idx = t + 256 * j;
                int r = idx >> 4, c4 = idx & 15;
                float4 v = ((const float4*)(W_pre + (size_t)(kc + r) * 64))[c4];
                float4 w;
                w.x = tf32f(v.x); w.y = tf32f(v.y); w.z = tf32f(v.z); w.w = tf32f(v.w);
                *(float4*)(Bs + r * NB + c4 * 4) = w;
            }
            int ck = t >> 5, cr = lane;
            Bs[cr * NB + 64 + ck] = tf32f(centroids[(size_t)ck * DIN + kc + cr]);
        }
        __syncthreads();
        /* MMA: warp computes its 16x72 tile */
        #pragma unroll
        for (int kk = 0; kk < 32; kk += 8) {
            uint32_t a0 = __float_as_uint(xs[(wrow + gid    ) * XS_STRIDE + kk + tig    ]);
            uint32_t a1 = __float_as_uint(xs[(wrow + gid + 8) * XS_STRIDE + kk + tig    ]);
            uint32_t a2 = __float_as_uint(xs[(wrow + gid    ) * XS_STRIDE + kk + tig + 4]);
            uint32_t a3 = __float_as_uint(xs[(wrow + gid + 8) * XS_STRIDE + kk + tig + 4]);
            #pragma unroll
            for (int nt = 0; nt < 9; nt++) {
                uint32_t b0 = __float_as_uint(Bs[(kk + tig    ) * NB + nt * 8 + gid]);
                uint32_t b1 = __float_as_uint(Bs[(kk + tig + 4) * NB + nt * 8 + gid]);
                mma8(acc[nt], a0, a1, a2, a3, b0, b1);
            }
        }
    }
    __syncthreads();
    /* stash accumulators into smem epilogue tile */
    #pragma unroll
    for (int nt = 0; nt < 9; nt++) {
        int c0 = nt * 8 + 2 * tig;
        ep[(wrow + gid    ) * EP_STRIDE + c0    ] = acc[nt][0];
        ep[(wrow + gid    ) * EP_STRIDE + c0 + 1] = acc[nt][1];
        ep[(wrow + gid + 8) * EP_STRIDE + c0    ] = acc[nt][2];
        ep[(wrow + gid + 8) * EP_STRIDE + c0 + 1] = acc[nt][3];
    }
    x2p[t] = x2acc;
    __syncthreads();
    /* vectorized relu(+bias) store to both output copies */
    {
        const int cb = (t & 1) * 32;
        #pragma unroll
        for (int i = 0; i < 8; i++) {
            int c = cb + 4 * i;
            float4 v = *(const float4*)(ep + lrow * EP_STRIDE + c);
            float4 b = *(const float4*)(b_pre + c);
            v.x = fmaxf(v.x + b.x, 0.f); v.y = fmaxf(v.y + b.y, 0.f);
            v.z = fmaxf(v.z + b.z, 0.f); v.w = fmaxf(v.w + b.w, 0.f);
            size_t go = (size_t)(rowBase + lrow) * 64 + c;
            *(float4*)(O1 + go) = v;
            *(float4*)(O2 + go) = v;
        }
    }
    /* hard assignment: softmax(1e7/dist) > 0.5  <=>  s < 2 at argmax */
    if (t < 128) {
        float x2 = x2p[2*t] + x2p[2*t + 1];
        float z[8], m = -3.4e38f;
        #pragma unroll
        for (int k = 0; k < 8; k++) {
            float dot = ep[t * EP_STRIDE + 64 + k];
            float d2  = fmaxf(x2 + c2s[k] - 2.0f * dot, 0.0f);
            float zk  = 1e7f / sqrtf(d2);
            z[k] = zk; m = fmaxf(m, zk);
        }
        float s = 0.f; int am = 0;
        #pragma unroll
        for (int k = 0; k < 8; k++) { s += expf(z[k] - m); if (z[k] == m) am = k; }
        sAssign[t] = (s < 2.0f) ? (unsigned char)am : (unsigned char)255;
    }
    __syncthreads();

    /* ---- fused cluster pooling: per-warp predicated reg partials ---- */
    const int nSeg0 = rowBase / P_PATCH;
    const int nSeg1 = (rowBase + M_TILE - 1) / P_PATCH;
    for (int seg = nSeg0; seg <= nSeg1; seg++) {
        const int lo = seg * P_PATCH, hi = lo + P_PATCH;
        #pragma unroll
        for (int cp = 0; cp < 2; cp++) {
            const int col = cp * 32 + lane;
            const float bias = b_pre[col];
            float pa[8];
            #pragma unroll
            for (int k = 0; k < 8; k++) pa[k] = 0.f;
            int cntMine = 0;   /* count for cluster == lane (lane<8) */
            #pragma unroll
            for (int i = 0; i < 16; i++) {
                const int lr = wrow + i;
                const int gr = rowBase + lr;
                int a = (gr >= lo && gr < hi) ? (int)sAssign[lr] : 255;
                float v = fmaxf(ep[lr * EP_STRIDE + col] + bias, 0.f);
                #pragma unroll
                for (int k = 0; k < 8; k++) pa[k] += (a == k) ? v : 0.f;
                cntMine += (a == lane) ? 1 : 0;
            }
            #pragma unroll
            for (int k = 0; k < 8; k++) part[warp][k][lane] = pa[k];
            if (cp == 0 && lane < 8 && cntMine > 0)
                atomicAdd(&g_counts[seg * 8 + lane], cntMine);
            __syncthreads();
            /* cross-warp reduce: thread t handles (k = t>>5, c = t&31) */
            {
                const int kk = t >> 5, cc = t & 31;
                float s = 0.f;
                #pragma unroll
                for (int w = 0; w < 8; w++) s += part[w][kk][cc];
                if (s != 0.f)
                    atomicAdd(&g_S[(seg * 8 + kk) * 64 + cp * 32 + cc], s);
            }
            __syncthreads();
        }
    }
}

/* ------------------------------------------------------------------ */
/* Kernel 3: attention MLP + masked softmax + enc_cls (tiny).         */
/* ------------------------------------------------------------------ */
__global__ __launch_bounds__(128) void k3(
    const float* __restrict__ W_a1, const float* __restrict__ b_a1,
    const float* __restrict__ W_a2, const float* __restrict__ b_a2,
    const float* __restrict__ W_out, const float* __restrict__ b_out,
    float* __restrict__ out)
{
    __shared__ float Aa[4][8];
    __shared__ float pool[4][64];
    const int t = threadIdx.x, n = t >> 5, lane = t & 31;

    for (int k = 0; k < 8; k++) {
        int cnt = g_counts[n * 8 + k];
        float inv = cnt > 0 ? 1.0f / (float)cnt : 0.0f;
        const float* S = g_S + (n * 8 + k) * 64;
        float h = b_a1[lane];
        #pragma unroll
        for (int d = 0; d < 64; d++) h = fmaf(S[d] * inv, W_a1[d * 32 + lane], h);
        h = tanhf(h);
        float c = h * W_a2[lane];
        #pragma unroll
        for (int o = 16; o; o >>= 1) c += __shfl_xor_sync(0xffffffffu, c, o);
        if (lane == 0) Aa[n][k] = (cnt > 0) ? (c + b_a2[0]) : -100000.0f;
    }
    __syncwarp();
    float m = -3.4e38f;
    #pragma unroll
    for (int k = 0; k < 8; k++) m = fmaxf(m, Aa[n][k]);
    float e[8], s = 0.f;
    #pragma unroll
    for (int k = 0; k < 8; k++) { e[k] = expf(Aa[n][k] - m); s += e[k]; }
    float p0 = 0.f, p1 = 0.f;
    #pragma unroll
    for (int k = 0; k < 8; k++) {
        int cnt = g_counts[n * 8 + k];
        float inv = cnt > 0 ? 1.0f / (float)cnt : 0.0f;
        float w = (e[k] / s) * inv;
        p0 = fmaf(g_S[(n * 8 + k) * 64 + lane     ], w, p0);
        p1 = fmaf(g_S[(n * 8 + k) * 64 + lane + 32], w, p1);
    }
    pool[n][lane] = p0; pool[n][lane + 32] = p1;
    __syncwarp();
    float ec = b_out[lane];
    #pragma unroll
    for (int d = 0; d < 64; d++) ec = fmaf(pool[n][d], W_out[d * 32 + lane], ec);
    out[n * 32 + lane] = fmaxf(ec, 0.f);
}

/* ------------------------------------------------------------------ */
extern "C" void kernel_launch(void* const* d_in, const int* in_sizes, int n_in,
                              void* d_out, int out_size)
{
    const float* x         = (const float*)d_in[0];
    const float* centroids = (const float*)d_in[1];
    const float* W_pre     = (const float*)d_in[2];
    const float* b_pre     = (const float*)d_in[3];
    const float* W_a1      = (const float*)d_in[4];
    const float* b_a1      = (const float*)d_in[5];
    const float* W_a2      = (const float*)d_in[6];
    const float* b_a2      = (const float*)d_in[7];
    const float* W_out     = (const float*)d_in[8];
    const float* b_out     = (const float*)d_in[9];

    float* out = (float*)d_out;
    float* O1 = out + 128;                         /* enc_seq copy 1 */
    float* O2 = out + 128 + (size_t)ROWS * 64;     /* enc_seq copy 2 */

    k0<<<1, 256>>>(centroids);
    k1<<<GRID1, 256>>>(x, centroids, W_pre, b_pre, O1, O2);
    k3<<<1, 128>>>(W_a1, b_a1, W_a2, b_a2, W_out, b_out, out);
}

// round 5
// speedup vs baseline: 2.6741x; 1.2726x over previous
#include <cuda_runtime.h>
#include <cstdint>

#define N_BAGS 4
#define P_PATCH 20000
#define DIN 1024
#define ROWS (N_BAGS*P_PATCH)   /* 80000 */
#define M_TILE 128
#define GRID1 (ROWS/M_TILE)     /* 625, exact */
#define NB 72                   /* 64 proj cols + 8 centroid cols */
#define XS_STRIDE 36
#define EP_STRIDE 76
#define BUF_FLOATS (M_TILE*XS_STRIDE + 32*NB)   /* 4608 + 2304 = 6912 */
#define SMEM_BYTES ((2*BUF_FLOATS + 2048 + 128 + 8 + 64) * 4)

/* scratch (no allocation allowed). Zero at module load; k3 re-zeroes at end
   of every call, so every kernel_launch invocation sees zeros (invariant). */
__device__ float g_S[32*64];
__device__ int   g_counts[32];

static __device__ __forceinline__ uint32_t tf32_bits(float f){
    uint32_t u; asm("cvt.rna.tf32.f32 %0, %1;" : "=r"(u) : "f"(f)); return u;
}

static __device__ __forceinline__ void mma8(float* c,
    uint32_t a0, uint32_t a1, uint32_t a2, uint32_t a3, uint32_t b0, uint32_t b1)
{
    asm volatile(
      "mma.sync.aligned.m16n8k8.row.col.f32.tf32.tf32.f32 "
      "{%0,%1,%2,%3},{%4,%5,%6,%7},{%8,%9},{%0,%1,%2,%3};\n"
      : "+f"(c[0]), "+f"(c[1]), "+f"(c[2]), "+f"(c[3])
      : "r"(a0), "r"(a1), "r"(a2), "r"(a3), "r"(b0), "r"(b1));
}

static __device__ __forceinline__ void cpa16(float* dst, const float* src){
    uint32_t d = (uint32_t)__cvta_generic_to_shared(dst);
    asm volatile("cp.async.cg.shared.global [%0], [%1], 16;\n" :: "r"(d), "l"(src));
}
static __device__ __forceinline__ void cpa4(float* dst, const float* src){
    uint32_t d = (uint32_t)__cvta_generic_to_shared(dst);
    asm volatile("cp.async.ca.shared.global [%0], [%1], 4;\n" :: "r"(d), "l"(src));
}
#define CP_COMMIT   asm volatile("cp.async.commit_group;\n" ::: "memory")
#define CP_WAIT1    asm volatile("cp.async.wait_group 1;\n" ::: "memory")
#define CP_WAIT0    asm volatile("cp.async.wait_group 0;\n" ::: "memory")

/* ------------------------------------------------------------------ */
/* Kernel 1: cp.async double-buffered  xp = relu(x@Wpre+b) (dual      */
/* store), centroid dots -> hard assignment, fused cluster pooling.   */
/* ------------------------------------------------------------------ */
__global__ __launch_bounds__(256, 3) void k1(
    const float* __restrict__ x, const float* __restrict__ centroids,
    const float* __restrict__ W_pre, const float* __restrict__ b_pre,
    float* __restrict__ O1, float* __restrict__ O2)
{
    extern __shared__ float sp[];
    float* ep   = sp;                       /* [128][76] epilogue (aliases bufs) */
    float* part = sp + 2*BUF_FLOATS;        /* [8][8][32] pooling partials */
    float* x2p  = part + 2048;              /* [128] per-row x^2 */
    float* c2s  = x2p + 128;                /* [8] centroid norms */
    unsigned char* sAssign = (unsigned char*)(c2s + 8);  /* [128] */

    const int t = threadIdx.x, warp = t >> 5, lane = t & 31;
    const int gid = lane >> 2, tig = lane & 3;
    const int rowBase = blockIdx.x * M_TILE;
    const int lrow = t >> 1, lcb = (t & 1) * 16;
    const int wrow = warp * 16;

    /* exact fp32 centroid norms: warp w handles centroid w */
    {
        float s = 0.f;
        const float* c = centroids + (size_t)warp * DIN;
        #pragma unroll
        for (int d = 0; d < DIN/32; d++) { float v = c[lane + 32*d]; s = fmaf(v, v, s); }
        #pragma unroll
        for (int o = 16; o; o >>= 1) s += __shfl_xor_sync(0xffffffffu, s, o);
        if (lane == 0) c2s[warp] = s;
    }

    float acc[9][4];
    #pragma unroll
    for (int i = 0; i < 9; i++) { acc[i][0]=acc[i][1]=acc[i][2]=acc[i][3]=0.f; }
    float x2a = 0.f, x2b = 0.f;   /* x^2 partials for rows wrow+gid, wrow+gid+8 */

    const float* xg0 = x + (size_t)(rowBase + lrow) * DIN + lcb;
    const float* wg0 = W_pre;
    const float* cg0 = centroids + (size_t)warp * DIN + lane;

    /* prefetch chunk 0 into buffer 0 */
    {
        float* xs = sp, * Bs = sp + M_TILE*XS_STRIDE;
        #pragma unroll
        for (int i = 0; i < 4; i++)
            cpa16(xs + lrow*XS_STRIDE + lcb + 4*i, xg0 + 4*i);
        #pragma unroll
        for (int j = 0; j < 2; j++) {
            int idx = t + 256*j, r = idx >> 4, c4 = idx & 15;
            cpa16(Bs + r*NB + c4*4, wg0 + (size_t)r*64 + c4*4);
        }
        cpa4(Bs + lane*NB + 64 + warp, cg0);
        CP_COMMIT;
    }

    #pragma unroll 1
    for (int i = 0; i < 32; i++) {
        if (i < 31) {   /* prefetch chunk i+1 into the other buffer */
            const int kcEl = (i + 1) * 32;
            float* xs = sp + ((i+1)&1)*BUF_FLOATS, * Bs = xs + M_TILE*XS_STRIDE;
            #pragma unroll
            for (int j = 0; j < 4; j++)
                cpa16(xs + lrow*XS_STRIDE + lcb + 4*j, xg0 + kcEl + 4*j);
            #pragma unroll
            for (int j = 0; j < 2; j++) {
                int idx = t + 256*j, r = idx >> 4, c4 = idx & 15;
                cpa16(Bs + r*NB + c4*4, wg0 + (size_t)(kcEl + r)*64 + c4*4);
            }
            cpa4(Bs + lane*NB + 64 + warp, cg0 + kcEl);
            CP_COMMIT;
            CP_WAIT1;
        } else {
            CP_WAIT0;
        }
        __syncthreads();
        /* MMA on buffer i&1 (cvt to tf32 in-register, x^2 on the fly) */
        {
            const float* xs = sp + (i&1)*BUF_FLOATS;
            const float* Bs = xs + M_TILE*XS_STRIDE;
            #pragma unroll
            for (int kk = 0; kk < 32; kk += 8) {
                float a0 = xs[(wrow + gid    ) * XS_STRIDE + kk + tig    ];
                float a1 = xs[(wrow + gid + 8) * XS_STRIDE + kk + tig    ];
                float a2 = xs[(wrow + gid    ) * XS_STRIDE + kk + tig + 4];
                float a3 = xs[(wrow + gid + 8) * XS_STRIDE + kk + tig + 4];
                x2a = fmaf(a0, a0, fmaf(a2, a2, x2a));
                x2b = fmaf(a1, a1, fmaf(a3, a3, x2b));
                uint32_t A0 = tf32_bits(a0), A1 = tf32_bits(a1);
                uint32_t A2 = tf32_bits(a2), A3 = tf32_bits(a3);
                #pragma unroll
                for (int nt = 0; nt < 9; nt++) {
                    uint32_t b0 = tf32_bits(Bs[(kk + tig    ) * NB + nt*8 + gid]);
                    uint32_t b1 = tf32_bits(Bs[(kk + tig + 4) * NB + nt*8 + gid]);
                    mma8(acc[nt], A0, A1, A2, A3, b0, b1);
                }
            }
        }
        __syncthreads();
    }

    /* reduce x^2 across the 4 tig lanes of each row pair */
    x2a += __shfl_xor_sync(0xffffffffu, x2a, 1);
    x2a += __shfl_xor_sync(0xffffffffu, x2a, 2);
    x2b += __shfl_xor_sync(0xffffffffu, x2b, 1);
    x2b += __shfl_xor_sync(0xffffffffu, x2b, 2);
    if (tig == 0) { x2p[wrow + gid] = x2a; x2p[wrow + gid + 8] = x2b; }

    /* stash accumulators into smem epilogue tile */
    #pragma unroll
    for (int nt = 0; nt < 9; nt++) {
        int c0 = nt * 8 + 2 * tig;
        ep[(wrow + gid    ) * EP_STRIDE + c0    ] = acc[nt][0];
        ep[(wrow + gid    ) * EP_STRIDE + c0 + 1] = acc[nt][1];
        ep[(wrow + gid + 8) * EP_STRIDE + c0    ] = acc[nt][2];
        ep[(wrow + gid + 8) * EP_STRIDE + c0 + 1] = acc[nt][3];
    }
    __syncthreads();
    /* vectorized relu(+bias) store to both output copies */
    {
        const int cb = (t & 1) * 32;
        #pragma unroll
        for (int i = 0; i < 8; i++) {
            int c = cb + 4 * i;
            float4 v = *(const float4*)(ep + lrow * EP_STRIDE + c);
            float4 b = *(const float4*)(b_pre + c);
            v.x = fmaxf(v.x + b.x, 0.f); v.y = fmaxf(v.y + b.y, 0.f);
            v.z = fmaxf(v.z + b.z, 0.f); v.w = fmaxf(v.w + b.w, 0.f);
            size_t go = (size_t)(rowBase + lrow) * 64 + c;
            *(float4*)(O1 + go) = v;
            *(float4*)(O2 + go) = v;
        }
    }
    /* hard assignment: softmax(1e7/dist) > 0.5  <=>  s < 2 at argmax */
    if (t < 128) {
        float x2 = x2p[t];
        float z[8], m = -3.4e38f;
        #pragma unroll
        for (int k = 0; k < 8; k++) {
            float dot = ep[t * EP_STRIDE + 64 + k];
            float d2  = fmaxf(x2 + c2s[k] - 2.0f * dot, 0.0f);
            float zk  = 1e7f / sqrtf(d2);
            z[k] = zk; m = fmaxf(m, zk);
        }
        float s = 0.f; int am = 0;
        #pragma unroll
        for (int k = 0; k < 8; k++) { s += expf(z[k] - m); if (z[k] == m) am = k; }
        sAssign[t] = (s < 2.0f) ? (unsigned char)am : (unsigned char)255;
    }
    __syncthreads();

    /* ---- fused cluster pooling: per-warp predicated reg partials ---- */
    const int nSeg0 = rowBase / P_PATCH;
    const int nSeg1 = (rowBase + M_TILE - 1) / P_PATCH;
    for (int seg = nSeg0; seg <= nSeg1; seg++) {
        const int lo = seg * P_PATCH, hi = lo + P_PATCH;
        #pragma unroll
        for (int cp = 0; cp < 2; cp++) {
            const int col = cp * 32 + lane;
            const float bias = b_pre[col];
            float pa[8];
            #pragma unroll
            for (int k = 0; k < 8; k++) pa[k] = 0.f;
            int cntMine = 0;   /* count for cluster == lane (lane<8) */
            #pragma unroll
            for (int i = 0; i < 16; i++) {
                const int lr = wrow + i;
                const int gr = rowBase + lr;
                int a = (gr >= lo && gr < hi) ? (int)sAssign[lr] : 255;
                float v = fmaxf(ep[lr * EP_STRIDE + col] + bias, 0.f);
                #pragma unroll
                for (int k = 0; k < 8; k++) pa[k] += (a == k) ? v : 0.f;
                cntMine += (a == lane) ? 1 : 0;
            }
            #pragma unroll
            for (int k = 0; k < 8; k++) part[(warp*8 + k)*32 + lane] = pa[k];
            if (cp == 0 && lane < 8 && cntMine > 0)
                atomicAdd(&g_counts[seg * 8 + lane], cntMine);
            __syncthreads();
            /* cross-warp reduce: thread t handles (k = t>>5, c = t&31) */
            {
                const int kk = t >> 5, cc = t & 31;
                float s = 0.f;
                #pragma unroll
                for (int w = 0; w < 8; w++) s += part[(w*8 + kk)*32 + cc];
                if (s != 0.f)
                    atomicAdd(&g_S[(seg * 8 + kk) * 64 + cp * 32 + cc], s);
            }
            __syncthreads();
        }
    }
}

/* ------------------------------------------------------------------ */
/* Kernel 3: attention MLP + masked softmax + enc_cls (tiny).         */
/* Re-zeroes g_S / g_counts at the end (invariant for next call).     */
/* ------------------------------------------------------------------ */
__global__ __launch_bounds__(128) void k3(
    const float* __restrict__ W_a1, const float* __restrict__ b_a1,
    const float* __restrict__ W_a2, const float* __restrict__ b_a2,
    const float* __restrict__ W_out, const float* __restrict__ b_out,
    float* __restrict__ out)
{
    __shared__ float Aa[4][8];
    __shared__ float pool[4][64];
    const int t = threadIdx.x, n = t >> 5, lane = t & 31;

    for (int k = 0; k < 8; k++) {
        int cnt = g_counts[n * 8 + k];
        float inv = cnt > 0 ? 1.0f / (float)cnt : 0.0f;
        const float* S = g_S + (n * 8 + k) * 64;
        float h = b_a1[lane];
        #pragma unroll
        for (int d = 0; d < 64; d++) h = fmaf(S[d] * inv, W_a1[d * 32 + lane], h);
        h = tanhf(h);
        float c = h * W_a2[lane];
        #pragma unroll
        for (int o = 16; o; o >>= 1) c += __shfl_xor_sync(0xffffffffu, c, o);
        if (lane == 0) Aa[n][k] = (cnt > 0) ? (c + b_a2[0]) : -100000.0f;
    }
    __syncwarp();
    float m = -3.4e38f;
    #pragma unroll
    for (int k = 0; k < 8; k++) m = fmaxf(m, Aa[n][k]);
    float e[8], s = 0.f;
    #pragma unroll
    for (int k = 0; k < 8; k++) { e[k] = expf(Aa[n][k] - m); s += e[k]; }
    float p0 = 0.f, p1 = 0.f;
    #pragma unroll
    for (int k = 0; k < 8; k++) {
        int cnt = g_counts[n * 8 + k];
        float inv = cnt > 0 ? 1.0f / (float)cnt : 0.0f;
        float w = (e[k] / s) * inv;
        p0 = fmaf(g_S[(n * 8 + k) * 64 + lane     ], w, p0);
        p1 = fmaf(g_S[(n * 8 + k) * 64 + lane + 32], w, p1);
    }
    pool[n][lane] = p0; pool[n][lane + 32] = p1;
    __syncwarp();
    float ec = b_out[lane];
    #pragma unroll
    for (int d = 0; d < 64; d++) ec = fmaf(pool[n][d], W_out[d * 32 + lane], ec);
    out[n * 32 + lane] = fmaxf(ec, 0.f);

    /* all reads of g_S/g_counts are done -> reset for next invocation */
    __syncthreads();
    #pragma unroll
    for (int i = 0; i < 16; i++) g_S[t + 128 * i] = 0.f;
    if (t < 32) g_counts[t] = 0;
}

/* ------------------------------------------------------------------ */
extern "C" void kernel_launch(void* const* d_in, const int* in_sizes, int n_in,
                              void* d_out, int out_size)
{
    const float* x         = (const float*)d_in[0];
    const float* centroids = (const float*)d_in[1];
    const float* W_pre     = (const float*)d_in[2];
    const float* b_pre     = (const float*)d_in[3];
    const float* W_a1      = (const float*)d_in[4];
    const float* b_a1      = (const float*)d_in[5];
    const float* W_a2      = (const float*)d_in[6];
    const float* b_a2      = (const float*)d_in[7];
    const float* W_out     = (const float*)d_in[8];
    const float* b_out     = (const float*)d_in[9];

    float* out = (float*)d_out;
    float* O1 = out + 128;                         /* enc_seq copy 1 */
    float* O2 = out + 128 + (size_t)ROWS * 64;     /* enc_seq copy 2 */

    cudaFuncSetAttribute(k1, cudaFuncAttributeMaxDynamicSharedMemorySize, SMEM_BYTES);
    k1<<<GRID1, 256, SMEM_BYTES>>>(x, centroids, W_pre, b_pre, O1, O2);
    k3<<<1, 128>>>(W_a1, b_a1, W_a2, b_a2, W_out, b_out, out);
}